// round 14
// baseline (speedup 1.0000x reference)
#include <cuda_runtime.h>
#include <cuda_fp16.h>
#include <math_constants.h>

#define N_NODES 100000
#define KNB     32
#define DIM     64
#define DIM2    32        // half2 per feature row
#define OUT_COLS 448      // 3*128 + 64

#define GEMM_BLOCKS   782    // ceil(100000/128)
#define GATHER_BLOCKS 6250   // 100000/16 exact

// intermediate feature tables in fp16 (half2-packed), ping-pong
__device__ __half2 g_hA[N_NODES * DIM2];
__device__ __half2 g_hB[N_NODES * DIM2];
// fp16 copy of gather output (128 fp16 = 64 half2 per node)
__device__ __half2 g_f[N_NODES * 64];

// per-128-row-chunk readiness flags (gather -> gemm), zeroed each replay by gemm0
__device__ unsigned g_flagA[GEMM_BLOCKS];
__device__ unsigned g_flagB[GEMM_BLOCKS];

static __device__ __forceinline__ void pdl_trigger() {
#if defined(__CUDA_ARCH__) && __CUDA_ARCH__ >= 900
    cudaTriggerProgrammaticLaunchCompletion();
#endif
}
static __device__ __forceinline__ void pdl_wait() {
#if defined(__CUDA_ARCH__) && __CUDA_ARCH__ >= 900
    cudaGridDependencySynchronize();
#endif
}

static __device__ __forceinline__ __half2 shfl_xor_h2(__half2 v, int m) {
    unsigned u = *reinterpret_cast<unsigned*>(&v);
    u = __shfl_xor_sync(0xffffffffu, u, m);
    return *reinterpret_cast<__half2*>(&u);
}

static __device__ __forceinline__ void mma16816(float* d,
        unsigned a0, unsigned a1, unsigned a2, unsigned a3,
        unsigned b0, unsigned b1) {
    asm volatile(
        "mma.sync.aligned.m16n8k16.row.col.f32.f16.f16.f32 "
        "{%0,%1,%2,%3},{%4,%5,%6,%7},{%8,%9},{%0,%1,%2,%3};"
        : "+f"(d[0]), "+f"(d[1]), "+f"(d[2]), "+f"(d[3])
        : "r"(a0), "r"(a1), "r"(a2), "r"(a3), "r"(b0), "r"(b1));
}

// ---------------------------------------------------------------------------
// GEMM0: h = relu(x @ W0 + b0), x:[N,64] fp32; copies x into out[:,384:448].
// Also zeroes the chunk flags for this replay (ordered before any producer
// via the PDL chain). 128 rows / 256 threads per block.
// ---------------------------------------------------------------------------
__global__ void __launch_bounds__(256)
gemm0_kernel(const float* __restrict__ F,
             const float* __restrict__ W,
             const float* __restrict__ b,
             __half2* __restrict__ h,
             float* __restrict__ out)
{
    constexpr int K2 = 32;
    constexpr int AP = K2 + 4;

    __shared__ __half2 As[128 * AP];
    __shared__ __half2 Bs[64 * AP];
    __shared__ float   bsm[64];

    pdl_trigger();

    const int tid  = threadIdx.x;
    const int row0 = blockIdx.x * 128;

    if (tid == 0) {
        g_flagA[blockIdx.x] = 0u;
        g_flagB[blockIdx.x] = 0u;
    }

    #pragma unroll
    for (int i = tid; i < 128 * K2; i += 256) {
        const int r  = i >> 5;
        const int c2 = i & (K2 - 1);
        const int gr = row0 + r;
        float2 v = make_float2(0.0f, 0.0f);
        if (gr < N_NODES) {
            v = *reinterpret_cast<const float2*>(&F[(size_t)gr * 64 + 2 * c2]);
            *reinterpret_cast<float2*>(&out[(size_t)gr * OUT_COLS + 384 + 2 * c2]) = v;
        }
        As[r * AP + c2] = __float22half2_rn(v);
    }
    #pragma unroll
    for (int i = tid; i < 64 * K2; i += 256) {
        const int n  = i & 63;
        const int k2 = i >> 6;
        float2 wv = make_float2(W[(2 * k2) * 64 + n], W[(2 * k2 + 1) * 64 + n]);
        Bs[n * AP + k2] = __float22half2_rn(wv);
    }
    if (tid < 64) bsm[tid] = b[tid];
    __syncthreads();

    const int warp = tid >> 5;
    const int lane = tid & 31;
    const int rt   = warp & 3;
    const int ch   = warp >> 2;
    const int r    = lane >> 2;
    const int qc   = lane & 3;

    const unsigned* Asu = reinterpret_cast<const unsigned*>(As);
    const unsigned* Bsu = reinterpret_cast<const unsigned*>(Bs);

    float acc[2][4][4];
    #pragma unroll
    for (int tt = 0; tt < 2; tt++)
        #pragma unroll
        for (int nt = 0; nt < 4; nt++)
            #pragma unroll
            for (int j = 0; j < 4; j++) acc[tt][nt][j] = 0.0f;

    #pragma unroll
    for (int ks = 0; ks < 4; ks++) {
        const int kb = ks * 8;
        unsigned a[2][4];
        #pragma unroll
        for (int tt = 0; tt < 2; tt++) {
            const int ar0 = (rt * 32 + tt * 16 + r) * AP;
            const int ar1 = ar0 + 8 * AP;
            a[tt][0] = Asu[ar0 + kb + qc];
            a[tt][1] = Asu[ar1 + kb + qc];
            a[tt][2] = Asu[ar0 + kb + 4 + qc];
            a[tt][3] = Asu[ar1 + kb + 4 + qc];
        }
        #pragma unroll
        for (int nt = 0; nt < 4; nt++) {
            const int brow = ((ch * 4 + nt) * 8 + r) * AP;
            const unsigned b0 = Bsu[brow + kb + qc];
            const unsigned b1 = Bsu[brow + kb + 4 + qc];
            #pragma unroll
            for (int tt = 0; tt < 2; tt++)
                mma16816(acc[tt][nt], a[tt][0], a[tt][1], a[tt][2], a[tt][3], b0, b1);
        }
    }

    #pragma unroll
    for (int tt = 0; tt < 2; tt++) {
        const int gr0 = row0 + rt * 32 + tt * 16 + r;
        const int gr1 = gr0 + 8;
        #pragma unroll
        for (int nt = 0; nt < 4; nt++) {
            const int n0  = (ch * 4 + nt) * 8 + qc * 2;
            const int h2c = (ch * 4 + nt) * 4 + qc;
            const float bb0 = bsm[n0], bb1 = bsm[n0 + 1];
            if (gr0 < N_NODES) {
                float2 v = make_float2(fmaxf(acc[tt][nt][0] + bb0, 0.0f),
                                       fmaxf(acc[tt][nt][1] + bb1, 0.0f));
                h[(size_t)gr0 * DIM2 + h2c] = __float22half2_rn(v);
            }
            if (gr1 < N_NODES) {
                float2 v = make_float2(fmaxf(acc[tt][nt][2] + bb0, 0.0f),
                                       fmaxf(acc[tt][nt][3] + bb1, 0.0f));
                h[(size_t)gr1 * DIM2 + h2c] = __float22half2_rn(v);
            }
        }
    }
}

// ---------------------------------------------------------------------------
// GEMM128h: h = relu(Fh @ W + b), Fh:[N,128] fp16 (g_f), W:[128,64] fp32.
// Per-chunk flag sync: W/bias prologue runs immediately; the A-tile load
// spins only on THIS block's 128-row chunk readiness (not the whole grid).
// Deadlock-free: PDL trigger semantics guarantee all producer CTAs have
// launched before any block of this kernel is scheduled.
// ---------------------------------------------------------------------------
__global__ void __launch_bounds__(256)
gemm128h_kernel(const __half2* __restrict__ Fh,
                const float* __restrict__ W,
                const float* __restrict__ b,
                __half2* __restrict__ h,
                unsigned* __restrict__ flag)
{
    constexpr int K2 = 64;
    constexpr int AP = K2 + 4;

    __shared__ __half2 As[128 * AP];
    __shared__ __half2 Bs[64 * AP];
    __shared__ float   bsm[64];

    pdl_trigger();

    const int tid  = threadIdx.x;
    const int row0 = blockIdx.x * 128;

    // independent prologue: W tile + bias
    #pragma unroll
    for (int i = tid; i < 64 * K2; i += 256) {
        const int n  = i & 63;
        const int k2 = i >> 6;
        float2 wv = make_float2(W[(2 * k2) * 64 + n], W[(2 * k2 + 1) * 64 + n]);
        Bs[n * AP + k2] = __float22half2_rn(wv);
    }
    if (tid < 64) bsm[tid] = b[tid];

    // wait for THIS chunk's gather blocks (8 per chunk; last chunk has 2)
    const unsigned target = (unsigned)min(8, GATHER_BLOCKS - 8 * blockIdx.x);
    if (tid == 0) {
        while (atomicAdd(&flag[blockIdx.x], 0u) < target) { }
        __threadfence();
    }
    __syncthreads();

    #pragma unroll
    for (int i = tid; i < 128 * 16; i += 256) {
        const int r = i >> 4, q = i & 15;
        const int gr = row0 + r;
        uint4 v = make_uint4(0u, 0u, 0u, 0u);
        if (gr < N_NODES)
            v = __ldg(reinterpret_cast<const uint4*>(Fh + (size_t)gr * 64) + q);
        *reinterpret_cast<uint4*>(&As[r * AP + 4 * q]) = v;
    }
    __syncthreads();

    const int warp = tid >> 5;
    const int lane = tid & 31;
    const int rt   = warp & 3;
    const int ch   = warp >> 2;
    const int r    = lane >> 2;
    const int qc   = lane & 3;

    const unsigned* Asu = reinterpret_cast<const unsigned*>(As);
    const unsigned* Bsu = reinterpret_cast<const unsigned*>(Bs);

    float acc[2][4][4];
    #pragma unroll
    for (int tt = 0; tt < 2; tt++)
        #pragma unroll
        for (int nt = 0; nt < 4; nt++)
            #pragma unroll
            for (int j = 0; j < 4; j++) acc[tt][nt][j] = 0.0f;

    #pragma unroll
    for (int ks = 0; ks < 8; ks++) {
        const int kb = ks * 8;
        unsigned a[2][4];
        #pragma unroll
        for (int tt = 0; tt < 2; tt++) {
            const int ar0 = (rt * 32 + tt * 16 + r) * AP;
            const int ar1 = ar0 + 8 * AP;
            a[tt][0] = Asu[ar0 + kb + qc];
            a[tt][1] = Asu[ar1 + kb + qc];
            a[tt][2] = Asu[ar0 + kb + 4 + qc];
            a[tt][3] = Asu[ar1 + kb + 4 + qc];
        }
        #pragma unroll
        for (int nt = 0; nt < 4; nt++) {
            const int brow = ((ch * 4 + nt) * 8 + r) * AP;
            const unsigned b0 = Bsu[brow + kb + qc];
            const unsigned b1 = Bsu[brow + kb + 4 + qc];
            #pragma unroll
            for (int tt = 0; tt < 2; tt++)
                mma16816(acc[tt][nt], a[tt][0], a[tt][1], a[tt][2], a[tt][3], b0, b1);
        }
    }

    #pragma unroll
    for (int tt = 0; tt < 2; tt++) {
        const int gr0 = row0 + rt * 32 + tt * 16 + r;
        const int gr1 = gr0 + 8;
        #pragma unroll
        for (int nt = 0; nt < 4; nt++) {
            const int n0  = (ch * 4 + nt) * 8 + qc * 2;
            const int h2c = (ch * 4 + nt) * 4 + qc;
            const float bb0 = bsm[n0], bb1 = bsm[n0 + 1];
            if (gr0 < N_NODES) {
                float2 v = make_float2(fmaxf(acc[tt][nt][0] + bb0, 0.0f),
                                       fmaxf(acc[tt][nt][1] + bb1, 0.0f));
                h[(size_t)gr0 * DIM2 + h2c] = __float22half2_rn(v);
            }
            if (gr1 < N_NODES) {
                float2 v = make_float2(fmaxf(acc[tt][nt][2] + bb0, 0.0f),
                                       fmaxf(acc[tt][nt][3] + bb1, 0.0f));
                h[(size_t)gr1 * DIM2 + h2c] = __float22half2_rn(v);
            }
        }
    }
}

// ---------------------------------------------------------------------------
// Gather: one warp per TWO nodes, fp16 packed accumulation (products >= 0).
// N % 16 == 0 -> no partial blocks, no early returns (needed for block-wide
// flag arrival). If SIDE: write fp16 copy to g_f and signal the chunk flag.
// ---------------------------------------------------------------------------
template<bool SIDE>
__global__ void __launch_bounds__(256)
gather_kernel(const int*     __restrict__ idx,
              const float*   __restrict__ dist,
              const __half2* __restrict__ h_in,
              float*         __restrict__ out,
              int                         col_off,
              __half2*       __restrict__ fh,
              unsigned*      __restrict__ flag)
{
    pdl_trigger();

    const int warp = threadIdx.x >> 5;
    const int lane = threadIdx.x & 31;
    const int n0   = blockIdx.x * 16 + warp * 2;
    const int n1   = n0 + 1;

    const int g = lane >> 3;
    const int c = lane & 7;

    // independent prologue: indices, distances, weights
    const int   nbA = idx[(size_t)n0 * KNB + lane];
    const float wA  = __expf(-10.0f * dist[(size_t)n0 * KNB + lane]);
    const int   nbB = idx[(size_t)n1 * KNB + lane];
    const float wB  = __expf(-10.0f * dist[(size_t)n1 * KNB + lane]);

    // wait for producer (GEMM writing h_in)
    pdl_wait();

    const __half2 zero = __float2half2_rn(0.0f);
    __half2 sumA[4] = {zero, zero, zero, zero};
    __half2 mxA[4]  = {zero, zero, zero, zero};
    __half2 sumB[4] = {zero, zero, zero, zero};
    __half2 mxB[4]  = {zero, zero, zero, zero};

    #pragma unroll
    for (int t = 0; t < 8; t++) {
        const int src = 4 * t + g;
        const int   nkA = __shfl_sync(0xffffffffu, nbA, src);
        const float wfA = __shfl_sync(0xffffffffu, wA,  src);
        const int   nkB = __shfl_sync(0xffffffffu, nbB, src);
        const float wfB = __shfl_sync(0xffffffffu, wB,  src);

        const uint4 ga = __ldg(reinterpret_cast<const uint4*>(h_in + (size_t)nkA * DIM2) + c);
        const uint4 gb = __ldg(reinterpret_cast<const uint4*>(h_in + (size_t)nkB * DIM2) + c);

        const __half2 wkA = __float2half2_rn(wfA);
        const __half2 wkB = __float2half2_rn(wfB);
        const __half2* ha = reinterpret_cast<const __half2*>(&ga);
        const __half2* hb = reinterpret_cast<const __half2*>(&gb);
        #pragma unroll
        for (int j = 0; j < 4; j++) {
            const __half2 pa = __hmul2(ha[j], wkA);
            sumA[j] = __hadd2(sumA[j], pa);
            mxA[j]  = __hmax2(mxA[j], pa);
            const __half2 pb = __hmul2(hb[j], wkB);
            sumB[j] = __hadd2(sumB[j], pb);
            mxB[j]  = __hmax2(mxB[j], pb);
        }
    }

    #pragma unroll
    for (int j = 0; j < 4; j++) {
        sumA[j] = __hadd2(sumA[j], shfl_xor_h2(sumA[j], 8));
        mxA[j]  = __hmax2(mxA[j],  shfl_xor_h2(mxA[j],  8));
        sumB[j] = __hadd2(sumB[j], shfl_xor_h2(sumB[j], 8));
        mxB[j]  = __hmax2(mxB[j],  shfl_xor_h2(mxB[j],  8));
        sumA[j] = __hadd2(sumA[j], shfl_xor_h2(sumA[j], 16));
        mxA[j]  = __hmax2(mxA[j],  shfl_xor_h2(mxA[j],  16));
        sumB[j] = __hadd2(sumB[j], shfl_xor_h2(sumB[j], 16));
        mxB[j]  = __hmax2(mxB[j],  shfl_xor_h2(mxB[j],  16));
    }

    // epilogue: g0 -> n0 mean, g1 -> n0 max, g2 -> n1 mean, g3 -> n1 max
    const int  myNode = (g < 2) ? n0 : n1;
    const bool isMax  = (g & 1);

    const uint4 sg = __ldg(reinterpret_cast<const uint4*>(h_in + (size_t)myNode * DIM2) + c);
    const __half2* sh = reinterpret_cast<const __half2*>(&sg);
    const __half2* sv = (g == 0) ? sumA : (g == 1) ? mxA : (g == 2) ? sumB : mxB;

    float res[8];
    if (!isMax) {
        #pragma unroll
        for (int j = 0; j < 4; j++) {
            const float2 sf = __half22float2(sv[j]);
            const float2 se = __half22float2(sh[j]);
            res[2 * j]     = sf.x * (1.0f / KNB) - se.x;
            res[2 * j + 1] = sf.y * (1.0f / KNB) - se.y;
        }
    } else {
        #pragma unroll
        for (int j = 0; j < 4; j++) {
            const float2 mf = __half22float2(sv[j]);
            const float2 se = __half22float2(sh[j]);
            res[2 * j]     = mf.x - se.x;
            res[2 * j + 1] = mf.y - se.y;
        }
    }
    float* orow = out + (size_t)myNode * OUT_COLS + col_off + (isMax ? 64 : 0);
    reinterpret_cast<float4*>(orow + 8 * c)[0] = make_float4(res[0], res[1], res[2], res[3]);
    reinterpret_cast<float4*>(orow + 8 * c)[1] = make_float4(res[4], res[5], res[6], res[7]);

    if (SIDE) {
        uint4 pk;
        __half2* ph = reinterpret_cast<__half2*>(&pk);
        #pragma unroll
        for (int j = 0; j < 4; j++)
            ph[j] = __float22half2_rn(make_float2(res[2 * j], res[2 * j + 1]));
        reinterpret_cast<uint4*>(fh + (size_t)myNode * 64)[(isMax ? 8 : 0) + c] = pk;

        // signal chunk readiness (all warps' stores fenced before flag)
        __threadfence();
        __syncthreads();
        if (threadIdx.x == 0)
            atomicAdd(&flag[blockIdx.x >> 3], 1u);
    }
}

// ---------------------------------------------------------------------------
// PDL launch helper
// ---------------------------------------------------------------------------
template<typename Kern, typename... Args>
static inline void launch_pdl(Kern kern, int grid, int block, Args... args)
{
    cudaLaunchConfig_t cfg = {};
    cfg.gridDim  = dim3((unsigned)grid);
    cfg.blockDim = dim3((unsigned)block);
    cudaLaunchAttribute attr[1];
    attr[0].id = cudaLaunchAttributeProgrammaticStreamSerialization;
    attr[0].val.programmaticStreamSerializationAllowed = 1;
    cfg.attrs    = attr;
    cfg.numAttrs = 1;
    cudaLaunchKernelEx(&cfg, kern, args...);
}

// ---------------------------------------------------------------------------
// inputs: x, neighbour_indices, distancesq, W0,b0, W1,b1, W2,b2
// output: [N, 448] = [feats0(128) | feats1(128) | feats2(128) | x(64)]
// ---------------------------------------------------------------------------
extern "C" void kernel_launch(void* const* d_in, const int* in_sizes, int n_in,
                              void* d_out, int out_size)
{
    const float* x    = (const float*)d_in[0];
    const int*   idx  = (const int*)  d_in[1];
    const float* dist = (const float*)d_in[2];
    const float* W0   = (const float*)d_in[3];
    const float* b0   = (const float*)d_in[4];
    const float* W1   = (const float*)d_in[5];
    const float* b1   = (const float*)d_in[6];
    const float* W2   = (const float*)d_in[7];
    const float* b2   = (const float*)d_in[8];
    float* out = (float*)d_out;

    __half2 *hA, *hB, *fh;
    unsigned *fA, *fB;
    cudaGetSymbolAddress((void**)&hA, g_hA);
    cudaGetSymbolAddress((void**)&hB, g_hB);
    cudaGetSymbolAddress((void**)&fh, g_f);
    cudaGetSymbolAddress((void**)&fA, g_flagA);
    cudaGetSymbolAddress((void**)&fB, g_flagB);

    gemm0_kernel<<<GEMM_BLOCKS, 256>>>(x, W0, b0, hA, out);
    launch_pdl(gather_kernel<true>,  GATHER_BLOCKS, 256, idx, dist,
               (const __half2*)hA, out, 0, fh, fA);
    launch_pdl(gemm128h_kernel,      GEMM_BLOCKS,   256, (const __half2*)fh, W1, b1, hB, fA);
    launch_pdl(gather_kernel<true>,  GATHER_BLOCKS, 256, idx, dist,
               (const __half2*)hB, out, 128, fh, fB);
    launch_pdl(gemm128h_kernel,      GEMM_BLOCKS,   256, (const __half2*)fh, W2, b2, hA, fB);
    launch_pdl(gather_kernel<false>, GATHER_BLOCKS, 256, idx, dist,
               (const __half2*)hA, out, 256, (__half2*)nullptr, (unsigned*)nullptr);
}

// round 15
// speedup vs baseline: 1.1368x; 1.1368x over previous
#include <cuda_runtime.h>
#include <cuda_fp16.h>
#include <math_constants.h>

#define N_NODES 100000
#define KNB     32
#define DIM     64
#define DIM2    32        // half2 per feature row
#define OUT_COLS 448      // 3*128 + 64

// intermediate feature tables in fp16 (half2-packed), ping-pong
__device__ __half2 g_hA[N_NODES * DIM2];
__device__ __half2 g_hB[N_NODES * DIM2];
// fp16 copy of gather output (128 fp16 = 64 half2 per node)
__device__ __half2 g_f[N_NODES * 64];

static __device__ __forceinline__ void pdl_trigger() {
#if defined(__CUDA_ARCH__) && __CUDA_ARCH__ >= 900
    cudaTriggerProgrammaticLaunchCompletion();
#endif
}
static __device__ __forceinline__ void pdl_wait() {
#if defined(__CUDA_ARCH__) && __CUDA_ARCH__ >= 900
    cudaGridDependencySynchronize();
#endif
}

static __device__ __forceinline__ __half2 shfl_xor_h2(__half2 v, int m) {
    unsigned u = *reinterpret_cast<unsigned*>(&v);
    u = __shfl_xor_sync(0xffffffffu, u, m);
    return *reinterpret_cast<__half2*>(&u);
}

static __device__ __forceinline__ void mma16816(float* d,
        unsigned a0, unsigned a1, unsigned a2, unsigned a3,
        unsigned b0, unsigned b1) {
    asm volatile(
        "mma.sync.aligned.m16n8k16.row.col.f32.f16.f16.f32 "
        "{%0,%1,%2,%3},{%4,%5,%6,%7},{%8,%9},{%0,%1,%2,%3};"
        : "+f"(d[0]), "+f"(d[1]), "+f"(d[2]), "+f"(d[3])
        : "r"(a0), "r"(a1), "r"(a2), "r"(a3), "r"(b0), "r"(b1));
}

// ---------------------------------------------------------------------------
// GEMM0: h = relu(x @ W0 + b0), x:[N,64] fp32; copies x into out[:,384:448]
// (streaming store — never re-read on device). 128 rows / 256 threads.
// ---------------------------------------------------------------------------
__global__ void __launch_bounds__(256)
gemm0_kernel(const float* __restrict__ F,
             const float* __restrict__ W,
             const float* __restrict__ b,
             __half2* __restrict__ h,
             float* __restrict__ out)
{
    constexpr int K2 = 32;
    constexpr int AP = K2 + 4;

    __shared__ __half2 As[128 * AP];
    __shared__ __half2 Bs[64 * AP];
    __shared__ float   bsm[64];

    pdl_trigger();

    const int tid  = threadIdx.x;
    const int row0 = blockIdx.x * 128;

    #pragma unroll
    for (int i = tid; i < 128 * K2; i += 256) {
        const int r  = i >> 5;
        const int c2 = i & (K2 - 1);
        const int gr = row0 + r;
        float2 v = make_float2(0.0f, 0.0f);
        if (gr < N_NODES) {
            v = *reinterpret_cast<const float2*>(&F[(size_t)gr * 64 + 2 * c2]);
            __stcs(reinterpret_cast<float2*>(&out[(size_t)gr * OUT_COLS + 384 + 2 * c2]), v);
        }
        As[r * AP + c2] = __float22half2_rn(v);
    }
    #pragma unroll
    for (int i = tid; i < 64 * K2; i += 256) {
        const int n  = i & 63;
        const int k2 = i >> 6;
        float2 wv = make_float2(W[(2 * k2) * 64 + n], W[(2 * k2 + 1) * 64 + n]);
        Bs[n * AP + k2] = __float22half2_rn(wv);
    }
    if (tid < 64) bsm[tid] = b[tid];
    __syncthreads();

    const int warp = tid >> 5;
    const int lane = tid & 31;
    const int rt   = warp & 3;
    const int ch   = warp >> 2;
    const int r    = lane >> 2;
    const int qc   = lane & 3;

    const unsigned* Asu = reinterpret_cast<const unsigned*>(As);
    const unsigned* Bsu = reinterpret_cast<const unsigned*>(Bs);

    float acc[2][4][4];
    #pragma unroll
    for (int tt = 0; tt < 2; tt++)
        #pragma unroll
        for (int nt = 0; nt < 4; nt++)
            #pragma unroll
            for (int j = 0; j < 4; j++) acc[tt][nt][j] = 0.0f;

    #pragma unroll
    for (int ks = 0; ks < 4; ks++) {
        const int kb = ks * 8;
        unsigned a[2][4];
        #pragma unroll
        for (int tt = 0; tt < 2; tt++) {
            const int ar0 = (rt * 32 + tt * 16 + r) * AP;
            const int ar1 = ar0 + 8 * AP;
            a[tt][0] = Asu[ar0 + kb + qc];
            a[tt][1] = Asu[ar1 + kb + qc];
            a[tt][2] = Asu[ar0 + kb + 4 + qc];
            a[tt][3] = Asu[ar1 + kb + 4 + qc];
        }
        #pragma unroll
        for (int nt = 0; nt < 4; nt++) {
            const int brow = ((ch * 4 + nt) * 8 + r) * AP;
            const unsigned b0 = Bsu[brow + kb + qc];
            const unsigned b1 = Bsu[brow + kb + 4 + qc];
            #pragma unroll
            for (int tt = 0; tt < 2; tt++)
                mma16816(acc[tt][nt], a[tt][0], a[tt][1], a[tt][2], a[tt][3], b0, b1);
        }
    }

    #pragma unroll
    for (int tt = 0; tt < 2; tt++) {
        const int gr0 = row0 + rt * 32 + tt * 16 + r;
        const int gr1 = gr0 + 8;
        #pragma unroll
        for (int nt = 0; nt < 4; nt++) {
            const int n0  = (ch * 4 + nt) * 8 + qc * 2;
            const int h2c = (ch * 4 + nt) * 4 + qc;
            const float bb0 = bsm[n0], bb1 = bsm[n0 + 1];
            if (gr0 < N_NODES) {
                float2 v = make_float2(fmaxf(acc[tt][nt][0] + bb0, 0.0f),
                                       fmaxf(acc[tt][nt][1] + bb1, 0.0f));
                h[(size_t)gr0 * DIM2 + h2c] = __float22half2_rn(v);
            }
            if (gr1 < N_NODES) {
                float2 v = make_float2(fmaxf(acc[tt][nt][2] + bb0, 0.0f),
                                       fmaxf(acc[tt][nt][3] + bb1, 0.0f));
                h[(size_t)gr1 * DIM2 + h2c] = __float22half2_rn(v);
            }
        }
    }
}

// ---------------------------------------------------------------------------
// GEMM128h: h = relu(Fh @ W + b), Fh:[N,128] fp16 (g_f), W:[128,64] fp32.
// PDL: W/bias SMEM load runs pre-sync (independent); A tile (fh) waits.
// ---------------------------------------------------------------------------
__global__ void __launch_bounds__(256)
gemm128h_kernel(const __half2* __restrict__ Fh,
                const float* __restrict__ W,
                const float* __restrict__ b,
                __half2* __restrict__ h)
{
    constexpr int K2 = 64;
    constexpr int AP = K2 + 4;

    __shared__ __half2 As[128 * AP];
    __shared__ __half2 Bs[64 * AP];
    __shared__ float   bsm[64];

    pdl_trigger();

    const int tid  = threadIdx.x;
    const int row0 = blockIdx.x * 128;

    // independent prologue: W tile + bias
    #pragma unroll
    for (int i = tid; i < 64 * K2; i += 256) {
        const int n  = i & 63;
        const int k2 = i >> 6;
        float2 wv = make_float2(W[(2 * k2) * 64 + n], W[(2 * k2 + 1) * 64 + n]);
        Bs[n * AP + k2] = __float22half2_rn(wv);
    }
    if (tid < 64) bsm[tid] = b[tid];

    // wait for producer (gather writing fh), then load A tile
    pdl_wait();

    #pragma unroll
    for (int i = tid; i < 128 * 16; i += 256) {
        const int r = i >> 4, q = i & 15;
        const int gr = row0 + r;
        uint4 v = make_uint4(0u, 0u, 0u, 0u);
        if (gr < N_NODES)
            v = __ldg(reinterpret_cast<const uint4*>(Fh + (size_t)gr * 64) + q);
        *reinterpret_cast<uint4*>(&As[r * AP + 4 * q]) = v;
    }
    __syncthreads();

    const int warp = tid >> 5;
    const int lane = tid & 31;
    const int rt   = warp & 3;
    const int ch   = warp >> 2;
    const int r    = lane >> 2;
    const int qc   = lane & 3;

    const unsigned* Asu = reinterpret_cast<const unsigned*>(As);
    const unsigned* Bsu = reinterpret_cast<const unsigned*>(Bs);

    float acc[2][4][4];
    #pragma unroll
    for (int tt = 0; tt < 2; tt++)
        #pragma unroll
        for (int nt = 0; nt < 4; nt++)
            #pragma unroll
            for (int j = 0; j < 4; j++) acc[tt][nt][j] = 0.0f;

    #pragma unroll
    for (int ks = 0; ks < 8; ks++) {
        const int kb = ks * 8;
        unsigned a[2][4];
        #pragma unroll
        for (int tt = 0; tt < 2; tt++) {
            const int ar0 = (rt * 32 + tt * 16 + r) * AP;
            const int ar1 = ar0 + 8 * AP;
            a[tt][0] = Asu[ar0 + kb + qc];
            a[tt][1] = Asu[ar1 + kb + qc];
            a[tt][2] = Asu[ar0 + kb + 4 + qc];
            a[tt][3] = Asu[ar1 + kb + 4 + qc];
        }
        #pragma unroll
        for (int nt = 0; nt < 4; nt++) {
            const int brow = ((ch * 4 + nt) * 8 + r) * AP;
            const unsigned b0 = Bsu[brow + kb + qc];
            const unsigned b1 = Bsu[brow + kb + 4 + qc];
            #pragma unroll
            for (int tt = 0; tt < 2; tt++)
                mma16816(acc[tt][nt], a[tt][0], a[tt][1], a[tt][2], a[tt][3], b0, b1);
        }
    }

    #pragma unroll
    for (int tt = 0; tt < 2; tt++) {
        const int gr0 = row0 + rt * 32 + tt * 16 + r;
        const int gr1 = gr0 + 8;
        #pragma unroll
        for (int nt = 0; nt < 4; nt++) {
            const int n0  = (ch * 4 + nt) * 8 + qc * 2;
            const int h2c = (ch * 4 + nt) * 4 + qc;
            const float bb0 = bsm[n0], bb1 = bsm[n0 + 1];
            if (gr0 < N_NODES) {
                float2 v = make_float2(fmaxf(acc[tt][nt][0] + bb0, 0.0f),
                                       fmaxf(acc[tt][nt][1] + bb1, 0.0f));
                h[(size_t)gr0 * DIM2 + h2c] = __float22half2_rn(v);
            }
            if (gr1 < N_NODES) {
                float2 v = make_float2(fmaxf(acc[tt][nt][2] + bb0, 0.0f),
                                       fmaxf(acc[tt][nt][3] + bb1, 0.0f));
                h[(size_t)gr1 * DIM2 + h2c] = __float22half2_rn(v);
            }
        }
    }
}

// ---------------------------------------------------------------------------
// Gather: one warp per TWO nodes, fp16 packed accumulation (products >= 0).
// PDL: idx/dist loads + exp run pre-sync; h_in reads wait. out written with
// streaming stores (write-once, never re-read on device).
// ---------------------------------------------------------------------------
template<bool SIDE>
__global__ void __launch_bounds__(256)
gather_kernel(const int*     __restrict__ idx,
              const float*   __restrict__ dist,
              const __half2* __restrict__ h_in,
              float*         __restrict__ out,
              int                         col_off,
              __half2*       __restrict__ fh)
{
    pdl_trigger();

    const int warp = threadIdx.x >> 5;
    const int lane = threadIdx.x & 31;
    const int n0   = blockIdx.x * 16 + warp * 2;
    const int n1   = n0 + 1;
    if (n0 >= N_NODES) return;
    const bool has1 = (n1 < N_NODES);

    const int g = lane >> 3;
    const int c = lane & 7;

    // independent prologue: indices, distances, weights
    const int   nbA = idx[(size_t)n0 * KNB + lane];
    const float wA  = __expf(-10.0f * dist[(size_t)n0 * KNB + lane]);
    const int   nbB = has1 ? idx[(size_t)n1 * KNB + lane] : 0;
    const float wB  = has1 ? __expf(-10.0f * dist[(size_t)n1 * KNB + lane]) : 0.0f;

    // wait for producer (GEMM writing h_in)
    pdl_wait();

    const __half2 zero = __float2half2_rn(0.0f);
    __half2 sumA[4] = {zero, zero, zero, zero};
    __half2 mxA[4]  = {zero, zero, zero, zero};
    __half2 sumB[4] = {zero, zero, zero, zero};
    __half2 mxB[4]  = {zero, zero, zero, zero};

    #pragma unroll
    for (int t = 0; t < 8; t++) {
        const int src = 4 * t + g;
        const int   nkA = __shfl_sync(0xffffffffu, nbA, src);
        const float wfA = __shfl_sync(0xffffffffu, wA,  src);
        const int   nkB = __shfl_sync(0xffffffffu, nbB, src);
        const float wfB = __shfl_sync(0xffffffffu, wB,  src);

        const uint4 ga = __ldg(reinterpret_cast<const uint4*>(h_in + (size_t)nkA * DIM2) + c);
        const uint4 gb = __ldg(reinterpret_cast<const uint4*>(h_in + (size_t)nkB * DIM2) + c);

        const __half2 wkA = __float2half2_rn(wfA);
        const __half2 wkB = __float2half2_rn(wfB);
        const __half2* ha = reinterpret_cast<const __half2*>(&ga);
        const __half2* hb = reinterpret_cast<const __half2*>(&gb);
        #pragma unroll
        for (int j = 0; j < 4; j++) {
            const __half2 pa = __hmul2(ha[j], wkA);
            sumA[j] = __hadd2(sumA[j], pa);
            mxA[j]  = __hmax2(mxA[j], pa);
            const __half2 pb = __hmul2(hb[j], wkB);
            sumB[j] = __hadd2(sumB[j], pb);
            mxB[j]  = __hmax2(mxB[j], pb);
        }
    }

    #pragma unroll
    for (int j = 0; j < 4; j++) {
        sumA[j] = __hadd2(sumA[j], shfl_xor_h2(sumA[j], 8));
        mxA[j]  = __hmax2(mxA[j],  shfl_xor_h2(mxA[j],  8));
        sumB[j] = __hadd2(sumB[j], shfl_xor_h2(sumB[j], 8));
        mxB[j]  = __hmax2(mxB[j],  shfl_xor_h2(mxB[j],  8));
        sumA[j] = __hadd2(sumA[j], shfl_xor_h2(sumA[j], 16));
        mxA[j]  = __hmax2(mxA[j],  shfl_xor_h2(mxA[j],  16));
        sumB[j] = __hadd2(sumB[j], shfl_xor_h2(sumB[j], 16));
        mxB[j]  = __hmax2(mxB[j],  shfl_xor_h2(mxB[j],  16));
    }

    // epilogue: g0 -> n0 mean, g1 -> n0 max, g2 -> n1 mean, g3 -> n1 max
    const int  myNode = (g < 2) ? n0 : n1;
    const bool isMax  = (g & 1);
    if (g >= 2 && !has1) return;

    const uint4 sg = __ldg(reinterpret_cast<const uint4*>(h_in + (size_t)myNode * DIM2) + c);
    const __half2* sh = reinterpret_cast<const __half2*>(&sg);
    const __half2* sv = (g == 0) ? sumA : (g == 1) ? mxA : (g == 2) ? sumB : mxB;

    float res[8];
    if (!isMax) {
        #pragma unroll
        for (int j = 0; j < 4; j++) {
            const float2 sf = __half22float2(sv[j]);
            const float2 se = __half22float2(sh[j]);
            res[2 * j]     = sf.x * (1.0f / KNB) - se.x;
            res[2 * j + 1] = sf.y * (1.0f / KNB) - se.y;
        }
    } else {
        #pragma unroll
        for (int j = 0; j < 4; j++) {
            const float2 mf = __half22float2(sv[j]);
            const float2 se = __half22float2(sh[j]);
            res[2 * j]     = mf.x - se.x;
            res[2 * j + 1] = mf.y - se.y;
        }
    }
    float* orow = out + (size_t)myNode * OUT_COLS + col_off + (isMax ? 64 : 0);
    __stcs(&reinterpret_cast<float4*>(orow + 8 * c)[0],
           make_float4(res[0], res[1], res[2], res[3]));
    __stcs(&reinterpret_cast<float4*>(orow + 8 * c)[1],
           make_float4(res[4], res[5], res[6], res[7]));

    if (SIDE) {
        uint4 pk;
        __half2* ph = reinterpret_cast<__half2*>(&pk);
        #pragma unroll
        for (int j = 0; j < 4; j++)
            ph[j] = __float22half2_rn(make_float2(res[2 * j], res[2 * j + 1]));
        reinterpret_cast<uint4*>(fh + (size_t)myNode * 64)[(isMax ? 8 : 0) + c] = pk;
    }
}

// ---------------------------------------------------------------------------
// PDL launch helper
// ---------------------------------------------------------------------------
template<typename Kern, typename... Args>
static inline void launch_pdl(Kern kern, int grid, int block, Args... args)
{
    cudaLaunchConfig_t cfg = {};
    cfg.gridDim  = dim3((unsigned)grid);
    cfg.blockDim = dim3((unsigned)block);
    cudaLaunchAttribute attr[1];
    attr[0].id = cudaLaunchAttributeProgrammaticStreamSerialization;
    attr[0].val.programmaticStreamSerializationAllowed = 1;
    cfg.attrs    = attr;
    cfg.numAttrs = 1;
    cudaLaunchKernelEx(&cfg, kern, args...);
}

// ---------------------------------------------------------------------------
// inputs: x, neighbour_indices, distancesq, W0,b0, W1,b1, W2,b2
// output: [N, 448] = [feats0(128) | feats1(128) | feats2(128) | x(64)]
// ---------------------------------------------------------------------------
extern "C" void kernel_launch(void* const* d_in, const int* in_sizes, int n_in,
                              void* d_out, int out_size)
{
    const float* x    = (const float*)d_in[0];
    const int*   idx  = (const int*)  d_in[1];
    const float* dist = (const float*)d_in[2];
    const float* W0   = (const float*)d_in[3];
    const float* b0   = (const float*)d_in[4];
    const float* W1   = (const float*)d_in[5];
    const float* b1   = (const float*)d_in[6];
    const float* W2   = (const float*)d_in[7];
    const float* b2   = (const float*)d_in[8];
    float* out = (float*)d_out;

    __half2 *hA, *hB, *fh;
    cudaGetSymbolAddress((void**)&hA, g_hA);
    cudaGetSymbolAddress((void**)&hB, g_hB);
    cudaGetSymbolAddress((void**)&fh, g_f);

    const int gemm_blocks   = (N_NODES + 127) / 128;
    const int gather_blocks = (N_NODES + 15) / 16;

    gemm0_kernel<<<gemm_blocks, 256>>>(x, W0, b0, hA, out);
    launch_pdl(gather_kernel<true>,  gather_blocks, 256, idx, dist,
               (const __half2*)hA, out, 0, fh);
    launch_pdl(gemm128h_kernel,      gemm_blocks,   256, (const __half2*)fh, W1, b1, hB);
    launch_pdl(gather_kernel<true>,  gather_blocks, 256, idx, dist,
               (const __half2*)hB, out, 128, fh);
    launch_pdl(gemm128h_kernel,      gemm_blocks,   256, (const __half2*)fh, W2, b2, hA);
    launch_pdl(gather_kernel<false>, gather_blocks, 256, idx, dist,
               (const __half2*)hA, out, 256, (__half2*)nullptr);
}